// round 1
// baseline (speedup 1.0000x reference)
#include <cuda_runtime.h>
#include <cuda_bf16.h>

// ----------------------------------------------------------------------------
// NeighborAttention, restructured:
//   Qt[n,h,:]  = (h_V[n] @ W_Q^T)[32h:32h+32] @ W_K[32h:32h+32,:]   (scaled 1/sqrt(32))
//   logits     = Qt[n,h,:] . h_E[n,k,:]
//   attend     = masked softmax
//   ctx[n,h,:] = sum_k attend * h_E[n,k,:]
//   vout       = ctx_h @ W_V_h^T ; out = vout @ W_O^T
// This removes the 63-GFLOP per-edge projections entirely (h_E read once).
// ----------------------------------------------------------------------------

#define MAXN 30720
#define HDIM 128
#define KNB 32

// scratch (allocation-free: static device globals)
__device__ float g_Q[MAXN * 128];
__device__ float g_Qt[MAXN * 512];
__device__ float g_ctx[MAXN * 512];
__device__ float g_vout[MAXN * 128];

// ----------------------------------------------------------------------------
// Generic tiled SGEMM: C[M,Nc] = alpha * A[M,K] * op(B),  row-major.
//   TRANSB=0: op(B)[k][n] = B[k*ldb + n]
//   TRANSB=1: op(B)[k][n] = B[n*ldb + k]   (i.e. C = A @ B^T)
// Batched via blockIdx.z with element strides aB/bB/cB.
// BM=BN=64, BK=16, 256 threads, 4x4 per-thread tile.
// ----------------------------------------------------------------------------
template <bool TRANSB>
__global__ void __launch_bounds__(256) sgemm_kernel(
    const float* __restrict__ A, const float* __restrict__ B, float* __restrict__ C,
    int M, int Nc, int K, int lda, int ldb, int ldc,
    long long aB, long long bB, long long cB, float alpha)
{
    __shared__ float As[16][68];  // transposed A tile: As[k][m], padded
    __shared__ float Bs[16][68];  // Bs[k][n], padded

    const long long bz = blockIdx.z;
    A += bz * aB; B += bz * bB; C += bz * cB;

    const int m0 = blockIdx.y * 64;
    const int n0 = blockIdx.x * 64;
    const int t  = threadIdx.x;
    const int tm = t >> 4;   // 0..15
    const int tn = t & 15;   // 0..15

    float acc[4][4] = {};

    for (int k0 = 0; k0 < K; k0 += 16) {
        // --- load A tile (64 x 16), one float4 per thread, store transposed ---
        {
            int row = t >> 2;            // 0..63
            int kc4 = (t & 3) << 2;      // 0,4,8,12
            float4 v = make_float4(0.f, 0.f, 0.f, 0.f);
            int gr = m0 + row;
            if (gr < M) v = *(const float4*)&A[(long long)gr * lda + k0 + kc4];
            As[kc4 + 0][row] = v.x;
            As[kc4 + 1][row] = v.y;
            As[kc4 + 2][row] = v.z;
            As[kc4 + 3][row] = v.w;
        }
        // --- load B tile (16 x 64) ---
        if (!TRANSB) {
            int kr  = t >> 4;            // 0..15
            int nc4 = (t & 15) << 2;     // 0..60
            float4 v = make_float4(0.f, 0.f, 0.f, 0.f);
            if (n0 + nc4 < Nc) v = *(const float4*)&B[(long long)(k0 + kr) * ldb + n0 + nc4];
            *(float4*)&Bs[kr][nc4] = v;
        } else {
            #pragma unroll
            for (int i = 0; i < 4; i++) {
                int idx = t + 256 * i;   // 0..1023
                int n = idx >> 4;        // 0..63
                int k = idx & 15;
                float v = 0.f;
                if (n0 + n < Nc) v = B[(long long)(n0 + n) * ldb + k0 + k];
                Bs[k][n] = v;
            }
        }
        __syncthreads();

        #pragma unroll
        for (int kk = 0; kk < 16; kk++) {
            float4 a4 = *(const float4*)&As[kk][tm << 2];
            float4 b4 = *(const float4*)&Bs[kk][tn << 2];
            float av[4] = {a4.x, a4.y, a4.z, a4.w};
            float bv[4] = {b4.x, b4.y, b4.z, b4.w};
            #pragma unroll
            for (int i = 0; i < 4; i++)
                #pragma unroll
                for (int j = 0; j < 4; j++)
                    acc[i][j] += av[i] * bv[j];
        }
        __syncthreads();
    }

    #pragma unroll
    for (int i = 0; i < 4; i++) {
        int r = m0 + (tm << 2) + i;
        int c = n0 + (tn << 2);
        if (r < M && c < Nc) {
            float4 v = make_float4(acc[i][0] * alpha, acc[i][1] * alpha,
                                   acc[i][2] * alpha, acc[i][3] * alpha);
            *(float4*)&C[(long long)r * ldc + c] = v;
        }
    }
}

// ----------------------------------------------------------------------------
// Fused neighbor attention: one block (128 threads) per node.
//   logits[h,k] = Qt[n,h,:] . h_E[n,k,:]
//   attend = masked softmax(logits) * mask
//   ctx[n, h*128 + a] = sum_k attend[h,k] * h_E[n,k,a]
// E staged in smem with row stride 132 (conflict-free for float4 logits reads
// and scalar per-lane ctx reads).
// ----------------------------------------------------------------------------
__global__ void __launch_bounds__(128) attn_kernel(
    const float* __restrict__ hE, const int* __restrict__ mask,
    const float* __restrict__ Qt, float* __restrict__ ctx)
{
    __shared__ float Es[32 * 132];
    __shared__ float Qts[4 * 132];
    __shared__ float Ls[128];
    __shared__ float Asm[128];
    __shared__ int   msk[32];

    const int n = blockIdx.x;
    const int t = threadIdx.x;

    // --- stage E tile (32 x 128 fp32 = 16KB), coalesced float4 ---
    const float* e = hE + (long long)n * (KNB * HDIM);
    #pragma unroll
    for (int i = 0; i < 8; i++) {
        int idx4 = t + 128 * i;          // 0..1023
        int k  = idx4 >> 5;              // row
        int a4 = idx4 & 31;              // float4 within row
        float4 v = *(const float4*)&e[idx4 << 2];
        *(float4*)&Es[k * 132 + (a4 << 2)] = v;
    }
    // --- stage Qt (4 x 128) ---
    {
        const float* q = Qt + (long long)n * 512;
        int h  = t >> 5;
        int a4 = t & 31;
        *(float4*)&Qts[h * 132 + (a4 << 2)] = *(const float4*)&q[t << 2];
    }
    if (t < 32) msk[t] = mask[(long long)n * KNB + t];
    __syncthreads();

    // --- logits: warp pair covers 2 heads x 16 k each (E read 2x, not 4x) ---
    {
        int w = t >> 5, l = t & 31;
        int h = ((w >> 1) << 1) | (l >> 4);
        int k = ((w & 1) << 4) | (l & 15);
        const float* qp = &Qts[h * 132];
        const float* ep = &Es[k * 132];
        float s = 0.f;
        #pragma unroll
        for (int a4 = 0; a4 < 32; a4++) {
            float4 q4 = *(const float4*)&qp[a4 << 2];
            float4 e4 = *(const float4*)&ep[a4 << 2];
            s += q4.x * e4.x + q4.y * e4.y + q4.z * e4.z + q4.w * e4.w;
        }
        Ls[h * 32 + k] = s;
    }
    __syncthreads();

    // --- masked softmax: warp w handles head w ---
    {
        int w = t >> 5, l = t & 31;
        float x  = Ls[w * 32 + l];
        bool mv  = (msk[l] != 0);
        float xm = mv ? x : -3.402823466e+38f;
        float mx = xm;
        #pragma unroll
        for (int o = 16; o > 0; o >>= 1) mx = fmaxf(mx, __shfl_xor_sync(0xffffffffu, mx, o));
        float p = mv ? __expf(xm - mx) : 0.f;
        float sm = p;
        #pragma unroll
        for (int o = 16; o > 0; o >>= 1) sm += __shfl_xor_sync(0xffffffffu, sm, o);
        float inv = (sm > 0.f) ? (1.f / sm) : 0.f;
        Asm[w * 32 + l] = p * inv;
    }
    __syncthreads();

    // --- ctx: thread t owns column a=t; 4 head accumulators in registers ---
    {
        float c0 = 0.f, c1 = 0.f, c2 = 0.f, c3 = 0.f;
        #pragma unroll
        for (int k4 = 0; k4 < 8; k4++) {
            float4 a0 = *(const float4*)&Asm[0 * 32 + (k4 << 2)];
            float4 a1 = *(const float4*)&Asm[1 * 32 + (k4 << 2)];
            float4 a2 = *(const float4*)&Asm[2 * 32 + (k4 << 2)];
            float4 a3 = *(const float4*)&Asm[3 * 32 + (k4 << 2)];
            float w0[4] = {a0.x, a0.y, a0.z, a0.w};
            float w1[4] = {a1.x, a1.y, a1.z, a1.w};
            float w2[4] = {a2.x, a2.y, a2.z, a2.w};
            float w3[4] = {a3.x, a3.y, a3.z, a3.w};
            #pragma unroll
            for (int i = 0; i < 4; i++) {
                float ev = Es[((k4 << 2) + i) * 132 + t];
                c0 += w0[i] * ev;
                c1 += w1[i] * ev;
                c2 += w2[i] * ev;
                c3 += w3[i] * ev;
            }
        }
        float* cp = ctx + (long long)n * 512 + t;
        cp[0]   = c0;
        cp[128] = c1;
        cp[256] = c2;
        cp[384] = c3;
    }
}

// ----------------------------------------------------------------------------
extern "C" void kernel_launch(void* const* d_in, const int* in_sizes, int n_in,
                              void* d_out, int out_size)
{
    const float* hV   = (const float*)d_in[0];
    const float* hE   = (const float*)d_in[1];
    const int*   mask = (const int*)  d_in[2];
    const float* WQ   = (const float*)d_in[3];
    const float* WK   = (const float*)d_in[4];
    const float* WV   = (const float*)d_in[5];
    const float* WO   = (const float*)d_in[6];
    float*       out  = (float*)d_out;

    const int N = in_sizes[0] / HDIM;
    if (N <= 0) return;

    float *Q, *Qt, *Ctx, *Vout;
    cudaGetSymbolAddress((void**)&Q,    g_Q);
    cudaGetSymbolAddress((void**)&Qt,   g_Qt);
    cudaGetSymbolAddress((void**)&Ctx,  g_ctx);
    cudaGetSymbolAddress((void**)&Vout, g_vout);

    const int MB = (N + 63) / 64;
    const dim3 blk(256);
    const float inv_sqrt_d = 0.17677669529663687f;  // 1/sqrt(32)

    // 1) Q = h_V @ W_Q^T                         [N,128] = [N,128] x [128,128]^T
    sgemm_kernel<true><<<dim3(2, MB, 1), blk>>>(
        hV, WQ, Q, N, 128, 128, 128, 128, 128, 0, 0, 0, 1.f);

    // 2) Qt[n, h*128+b] = (1/sqrt(d)) * Q[n,32h:32h+32] @ W_K[32h:32h+32,:]
    sgemm_kernel<false><<<dim3(2, MB, 4), blk>>>(
        Q, WK, Qt, N, 128, 32, 128, 128, 512,
        /*aB=*/32, /*bB=*/32 * 128, /*cB=*/128, inv_sqrt_d);

    // 3) fused attention -> ctx[N,512]
    attn_kernel<<<N, 128>>>(hE, mask, Qt, Ctx);

    // 4) vout[n, 32h+j] = ctx[n, 128h:] @ W_V[32h+j,:]   (C = A @ B^T per head)
    sgemm_kernel<true><<<dim3(1, MB, 4), blk>>>(
        Ctx, WV, Vout, N, 32, 128, 512, 128, 128,
        /*aB=*/128, /*bB=*/32 * 128, /*cB=*/32, 1.f);

    // 5) out = vout @ W_O^T
    sgemm_kernel<true><<<dim3(2, MB, 1), blk>>>(
        Vout, WO, out, N, 128, 128, 128, 128, 128, 0, 0, 0, 1.f);
}

// round 2
// speedup vs baseline: 1.0999x; 1.0999x over previous
#include <cuda_runtime.h>
#include <cuda_bf16.h>

// ----------------------------------------------------------------------------
// NeighborAttention, restructured (63 GFLOP -> 3.9 GFLOP):
//   Qt[n,h,:]  = (1/sqrt(32)) * (h_V[n] @ W_Q^T)[32h:32h+32] @ W_K[32h:32h+32,:]
//   logits     = Qt[n,h,:] . h_E[n,k,:]
//   attend     = masked softmax
//   ctx[n,h,:] = sum_k attend * h_E[n,k,:]
//   vout       = ctx_h @ W_V_h^T ; out = vout @ W_O^T
// ----------------------------------------------------------------------------

#define MAXN 30720
#define HDIM 128
#define KNB 32

__device__ float g_Q[MAXN * 128];
__device__ float g_Qt[MAXN * 512];
__device__ float g_ctx[MAXN * 512];
__device__ float g_vout[MAXN * 128];

// ----------------------------------------------------------------------------
// Tiled SGEMM, 8-wide/4-wide register microtiles (4 FMA per smem word).
//   C[M,Nc] = alpha * A[M,K] * op(B), row-major; TRANSB=1 -> C = A @ B^T.
//   Batched via blockIdx.z with element strides aB/bB/cB.
// ----------------------------------------------------------------------------
template <int BM, int BN, int BK, int TM, int TN, bool TRANSB>
__global__ void __launch_bounds__((BM / TM) * (BN / TN)) sgemm_kernel(
    const float* __restrict__ A, const float* __restrict__ B, float* __restrict__ C,
    int M, int Nc, int K, int lda, int ldb, int ldc,
    long long aB, long long bB, long long cB, float alpha)
{
    constexpr int NT = (BM / TM) * (BN / TN);
    __shared__ float As[BK][BM + 4];
    __shared__ float Bs[BK][BN + 4];

    const long long bz = blockIdx.z;
    A += bz * aB; B += bz * bB; C += bz * cB;

    const int m0 = blockIdx.y * BM;
    const int n0 = blockIdx.x * BN;
    const int t  = threadIdx.x;
    const int tm = t / (BN / TN);
    const int tn = t % (BN / TN);

    float acc[TM][TN] = {};

    for (int k0 = 0; k0 < K; k0 += BK) {
        // ---- A tile (BM x BK), float4 along k, stored transposed As[k][m] ----
        constexpr int A4 = (BM * BK) / (4 * NT);
        #pragma unroll
        for (int i = 0; i < A4; i++) {
            int idx4 = t + NT * i;
            int r  = idx4 / (BK / 4);
            int kc = (idx4 % (BK / 4)) * 4;
            float4 v = make_float4(0.f, 0.f, 0.f, 0.f);
            int gr = m0 + r;
            if (gr < M) v = *(const float4*)&A[(long long)gr * lda + k0 + kc];
            As[kc + 0][r] = v.x;
            As[kc + 1][r] = v.y;
            As[kc + 2][r] = v.z;
            As[kc + 3][r] = v.w;
        }
        // ---- B tile ----
        if (!TRANSB) {
            constexpr int B4 = (BK * BN) / (4 * NT);
            #pragma unroll
            for (int i = 0; i < B4; i++) {
                int idx4 = t + NT * i;
                int kr = idx4 / (BN / 4);
                int nc = (idx4 % (BN / 4)) * 4;
                float4 v = make_float4(0.f, 0.f, 0.f, 0.f);
                if (n0 + nc < Nc) v = *(const float4*)&B[(long long)(k0 + kr) * ldb + n0 + nc];
                *(float4*)&Bs[kr][nc] = v;
            }
        } else {
            constexpr int B4 = (BN * BK) / (4 * NT);
            #pragma unroll
            for (int i = 0; i < B4; i++) {
                int idx4 = t + NT * i;
                int n  = idx4 / (BK / 4);
                int kc = (idx4 % (BK / 4)) * 4;
                float4 v = make_float4(0.f, 0.f, 0.f, 0.f);
                if (n0 + n < Nc) v = *(const float4*)&B[(long long)(n0 + n) * ldb + k0 + kc];
                Bs[kc + 0][n] = v.x;
                Bs[kc + 1][n] = v.y;
                Bs[kc + 2][n] = v.z;
                Bs[kc + 3][n] = v.w;
            }
        }
        __syncthreads();

        #pragma unroll
        for (int kk = 0; kk < BK; kk++) {
            float a[TM], b[TN];
            #pragma unroll
            for (int h = 0; h < TM / 4; h++) {
                float4 v = *(const float4*)&As[kk][tm * 4 + h * (BM / 2)];
                a[h * 4 + 0] = v.x; a[h * 4 + 1] = v.y;
                a[h * 4 + 2] = v.z; a[h * 4 + 3] = v.w;
            }
            #pragma unroll
            for (int h = 0; h < TN / 4; h++) {
                float4 v = *(const float4*)&Bs[kk][tn * 4 + h * (BN / 2)];
                b[h * 4 + 0] = v.x; b[h * 4 + 1] = v.y;
                b[h * 4 + 2] = v.z; b[h * 4 + 3] = v.w;
            }
            #pragma unroll
            for (int i = 0; i < TM; i++)
                #pragma unroll
                for (int j = 0; j < TN; j++)
                    acc[i][j] += a[i] * b[j];
        }
        __syncthreads();
    }

    // ---- epilogue ----
    #pragma unroll
    for (int i = 0; i < TM; i++) {
        int r = m0 + tm * 4 + (i / 4) * (BM / 2) + (i % 4);
        if (r >= M) continue;
        #pragma unroll
        for (int jh = 0; jh < TN / 4; jh++) {
            int c = n0 + tn * 4 + jh * (BN / 2);
            if (c < Nc) {
                float4 v = make_float4(acc[i][jh * 4 + 0] * alpha, acc[i][jh * 4 + 1] * alpha,
                                       acc[i][jh * 4 + 2] * alpha, acc[i][jh * 4 + 3] * alpha);
                *(float4*)&C[(long long)r * ldc + c] = v;
            }
        }
    }
}

// ----------------------------------------------------------------------------
// Fused neighbor attention: one block (128 threads) per node.
// ----------------------------------------------------------------------------
__global__ void __launch_bounds__(128) attn_kernel(
    const float* __restrict__ hE, const int* __restrict__ mask,
    const float* __restrict__ Qt, float* __restrict__ ctx)
{
    __shared__ float Es[32 * 132];
    __shared__ float Qts[4 * 132];
    __shared__ float Ls[128];
    __shared__ float Asm[128];
    __shared__ int   msk[32];

    const int n = blockIdx.x;
    const int t = threadIdx.x;

    const float* e = hE + (long long)n * (KNB * HDIM);
    #pragma unroll
    for (int i = 0; i < 8; i++) {
        int idx4 = t + 128 * i;
        int k  = idx4 >> 5;
        int a4 = idx4 & 31;
        float4 v = *(const float4*)&e[idx4 << 2];
        *(float4*)&Es[k * 132 + (a4 << 2)] = v;
    }
    {
        const float* q = Qt + (long long)n * 512;
        int h  = t >> 5;
        int a4 = t & 31;
        *(float4*)&Qts[h * 132 + (a4 << 2)] = *(const float4*)&q[t << 2];
    }
    if (t < 32) msk[t] = mask[(long long)n * KNB + t];
    __syncthreads();

    {
        int w = t >> 5, l = t & 31;
        int h = ((w >> 1) << 1) | (l >> 4);
        int k = ((w & 1) << 4) | (l & 15);
        const float* qp = &Qts[h * 132];
        const float* ep = &Es[k * 132];
        float s = 0.f;
        #pragma unroll
        for (int a4 = 0; a4 < 32; a4++) {
            float4 q4 = *(const float4*)&qp[a4 << 2];
            float4 e4 = *(const float4*)&ep[a4 << 2];
            s += q4.x * e4.x + q4.y * e4.y + q4.z * e4.z + q4.w * e4.w;
        }
        Ls[h * 32 + k] = s;
    }
    __syncthreads();

    {
        int w = t >> 5, l = t & 31;
        float x  = Ls[w * 32 + l];
        bool mv  = (msk[l] != 0);
        float xm = mv ? x : -3.402823466e+38f;
        float mx = xm;
        #pragma unroll
        for (int o = 16; o > 0; o >>= 1) mx = fmaxf(mx, __shfl_xor_sync(0xffffffffu, mx, o));
        float p = mv ? __expf(xm - mx) : 0.f;
        float sm = p;
        #pragma unroll
        for (int o = 16; o > 0; o >>= 1) sm += __shfl_xor_sync(0xffffffffu, sm, o);
        float inv = (sm > 0.f) ? (1.f / sm) : 0.f;
        Asm[w * 32 + l] = p * inv;
    }
    __syncthreads();

    {
        float c0 = 0.f, c1 = 0.f, c2 = 0.f, c3 = 0.f;
        #pragma unroll
        for (int k4 = 0; k4 < 8; k4++) {
            float4 a0 = *(const float4*)&Asm[0 * 32 + (k4 << 2)];
            float4 a1 = *(const float4*)&Asm[1 * 32 + (k4 << 2)];
            float4 a2 = *(const float4*)&Asm[2 * 32 + (k4 << 2)];
            float4 a3 = *(const float4*)&Asm[3 * 32 + (k4 << 2)];
            float w0[4] = {a0.x, a0.y, a0.z, a0.w};
            float w1[4] = {a1.x, a1.y, a1.z, a1.w};
            float w2[4] = {a2.x, a2.y, a2.z, a2.w};
            float w3[4] = {a3.x, a3.y, a3.z, a3.w};
            #pragma unroll
            for (int i = 0; i < 4; i++) {
                float ev = Es[((k4 << 2) + i) * 132 + t];
                c0 += w0[i] * ev;
                c1 += w1[i] * ev;
                c2 += w2[i] * ev;
                c3 += w3[i] * ev;
            }
        }
        float* cp = ctx + (long long)n * 512 + t;
        cp[0]   = c0;
        cp[128] = c1;
        cp[256] = c2;
        cp[384] = c3;
    }
}

// ----------------------------------------------------------------------------
extern "C" void kernel_launch(void* const* d_in, const int* in_sizes, int n_in,
                              void* d_out, int out_size)
{
    const float* hV   = (const float*)d_in[0];
    const float* hE   = (const float*)d_in[1];
    const int*   mask = (const int*)  d_in[2];
    const float* WQ   = (const float*)d_in[3];
    const float* WK   = (const float*)d_in[4];
    const float* WV   = (const float*)d_in[5];
    const float* WO   = (const float*)d_in[6];
    float*       out  = (float*)d_out;

    const int N = in_sizes[0] / HDIM;
    if (N <= 0) return;

    float *Q, *Qt, *Ctx, *Vout;
    cudaGetSymbolAddress((void**)&Q,    g_Q);
    cudaGetSymbolAddress((void**)&Qt,   g_Qt);
    cudaGetSymbolAddress((void**)&Ctx,  g_ctx);
    cudaGetSymbolAddress((void**)&Vout, g_vout);

    const int MB64  = (N + 63) / 64;
    const int MB128 = (N + 127) / 128;
    const float inv_sqrt_d = 0.17677669529663687f;  // 1/sqrt(32)

    // 1) Q = h_V @ W_Q^T
    sgemm_kernel<64, 128, 8, 8, 8, true><<<dim3(1, MB64, 1), 128>>>(
        hV, WQ, Q, N, 128, 128, 128, 128, 128, 0, 0, 0, 1.f);

    // 2) Qt[n, h*128+b] = (1/sqrt(d)) * Q[n,32h:32h+32] @ W_K[32h:32h+32,:]
    sgemm_kernel<64, 128, 8, 8, 8, false><<<dim3(1, MB64, 4), 128>>>(
        Q, WK, Qt, N, 128, 32, 128, 128, 512,
        /*aB=*/32, /*bB=*/32 * 128, /*cB=*/128, inv_sqrt_d);

    // 3) fused attention -> ctx[N,512]
    attn_kernel<<<N, 128>>>(hE, mask, Qt, Ctx);

    // 4) vout[n, 32h+j] = ctx[n, 128h:] @ W_V[32h+j,:]
    sgemm_kernel<128, 32, 16, 8, 4, true><<<dim3(1, MB128, 4), 128>>>(
        Ctx, WV, Vout, N, 32, 128, 512, 128, 128,
        /*aB=*/128, /*bB=*/32 * 128, /*cB=*/32, 1.f);

    // 5) out = vout @ W_O^T
    sgemm_kernel<64, 128, 8, 8, 8, true><<<dim3(1, MB64, 1), 128>>>(
        Vout, WO, out, N, 128, 128, 128, 128, 128, 0, 0, 0, 1.f);
}

// round 3
// speedup vs baseline: 1.1620x; 1.0564x over previous
#include <cuda_runtime.h>
#include <cuda_bf16.h>

// ----------------------------------------------------------------------------
// NeighborAttention, restructured (63 GFLOP -> 3.9 GFLOP):
//   Qt[n,h,:]  = (1/sqrt(32)) * (h_V[n] @ W_Q^T)[32h:32h+32] @ W_K[32h:32h+32,:]
//   logits     = Qt[n,h,:] . h_E[n,k,:]
//   attend     = masked softmax
//   ctx[n,h,:] = sum_k attend * h_E[n,k,:]
//   vout       = ctx_h @ W_V_h^T ; out = vout @ W_O^T
// ----------------------------------------------------------------------------

#define MAXN 30720
#define HDIM 128
#define KNB 32

__device__ float g_Q[MAXN * 128];
__device__ float g_Qt[MAXN * 512];
__device__ float g_ctx[MAXN * 512];
__device__ float g_vout[MAXN * 128];

// ----------------------------------------------------------------------------
// Tiled SGEMM, 8-wide/4-wide register microtiles.
// ----------------------------------------------------------------------------
template <int BM, int BN, int BK, int TM, int TN, bool TRANSB>
__global__ void __launch_bounds__((BM / TM) * (BN / TN)) sgemm_kernel(
    const float* __restrict__ A, const float* __restrict__ B, float* __restrict__ C,
    int M, int Nc, int K, int lda, int ldb, int ldc,
    long long aB, long long bB, long long cB, float alpha)
{
    constexpr int NT = (BM / TM) * (BN / TN);
    __shared__ float As[BK][BM + 4];
    __shared__ float Bs[BK][BN + 4];

    const long long bz = blockIdx.z;
    A += bz * aB; B += bz * bB; C += bz * cB;

    const int m0 = blockIdx.y * BM;
    const int n0 = blockIdx.x * BN;
    const int t  = threadIdx.x;
    const int tm = t / (BN / TN);
    const int tn = t % (BN / TN);

    float acc[TM][TN] = {};

    for (int k0 = 0; k0 < K; k0 += BK) {
        constexpr int A4 = (BM * BK) / (4 * NT);
        #pragma unroll
        for (int i = 0; i < A4; i++) {
            int idx4 = t + NT * i;
            int r  = idx4 / (BK / 4);
            int kc = (idx4 % (BK / 4)) * 4;
            float4 v = make_float4(0.f, 0.f, 0.f, 0.f);
            int gr = m0 + r;
            if (gr < M) v = *(const float4*)&A[(long long)gr * lda + k0 + kc];
            As[kc + 0][r] = v.x;
            As[kc + 1][r] = v.y;
            As[kc + 2][r] = v.z;
            As[kc + 3][r] = v.w;
        }
        if (!TRANSB) {
            constexpr int B4 = (BK * BN) / (4 * NT);
            #pragma unroll
            for (int i = 0; i < B4; i++) {
                int idx4 = t + NT * i;
                int kr = idx4 / (BN / 4);
                int nc = (idx4 % (BN / 4)) * 4;
                float4 v = make_float4(0.f, 0.f, 0.f, 0.f);
                if (n0 + nc < Nc) v = *(const float4*)&B[(long long)(k0 + kr) * ldb + n0 + nc];
                *(float4*)&Bs[kr][nc] = v;
            }
        } else {
            constexpr int B4 = (BN * BK) / (4 * NT);
            #pragma unroll
            for (int i = 0; i < B4; i++) {
                int idx4 = t + NT * i;
                int n  = idx4 / (BK / 4);
                int kc = (idx4 % (BK / 4)) * 4;
                float4 v = make_float4(0.f, 0.f, 0.f, 0.f);
                if (n0 + n < Nc) v = *(const float4*)&B[(long long)(n0 + n) * ldb + k0 + kc];
                Bs[kc + 0][n] = v.x;
                Bs[kc + 1][n] = v.y;
                Bs[kc + 2][n] = v.z;
                Bs[kc + 3][n] = v.w;
            }
        }
        __syncthreads();

        #pragma unroll
        for (int kk = 0; kk < BK; kk++) {
            float a[TM], b[TN];
            #pragma unroll
            for (int h = 0; h < TM / 4; h++) {
                float4 v = *(const float4*)&As[kk][tm * 4 + h * (BM / 2)];
                a[h * 4 + 0] = v.x; a[h * 4 + 1] = v.y;
                a[h * 4 + 2] = v.z; a[h * 4 + 3] = v.w;
            }
            #pragma unroll
            for (int h = 0; h < TN / 4; h++) {
                float4 v = *(const float4*)&Bs[kk][tn * 4 + h * (BN / 2)];
                b[h * 4 + 0] = v.x; b[h * 4 + 1] = v.y;
                b[h * 4 + 2] = v.z; b[h * 4 + 3] = v.w;
            }
            #pragma unroll
            for (int i = 0; i < TM; i++)
                #pragma unroll
                for (int j = 0; j < TN; j++)
                    acc[i][j] += a[i] * b[j];
        }
        __syncthreads();
    }

    #pragma unroll
    for (int i = 0; i < TM; i++) {
        int r = m0 + tm * 4 + (i / 4) * (BM / 2) + (i % 4);
        if (r >= M) continue;
        #pragma unroll
        for (int jh = 0; jh < TN / 4; jh++) {
            int c = n0 + tn * 4 + jh * (BN / 2);
            if (c < Nc) {
                float4 v = make_float4(acc[i][jh * 4 + 0] * alpha, acc[i][jh * 4 + 1] * alpha,
                                       acc[i][jh * 4 + 2] * alpha, acc[i][jh * 4 + 3] * alpha);
                *(float4*)&C[(long long)r * ldc + c] = v;
            }
        }
    }
}

// ----------------------------------------------------------------------------
// Fused neighbor attention, one block (128 threads) per node.
// Logits phase: thread = (k = lane, a-chunk = warp). Each E float4 read feeds
// 16 FMAs (4 heads); Qt reads are warp-uniform broadcasts. Partials reduced
// via conflict-free transposed buffer Lp[ac][h*32+k].
// ----------------------------------------------------------------------------
__global__ void __launch_bounds__(128) attn_kernel(
    const float* __restrict__ hE, const int* __restrict__ mask,
    const float* __restrict__ Qt, float* __restrict__ ctx)
{
    __shared__ float Es[32 * 132];
    __shared__ float Qts[4 * 132];
    __shared__ float Lp[512];      // [ac][h*32+k]
    __shared__ float Asm[128];
    __shared__ int   msk[32];

    const int n = blockIdx.x;
    const int t = threadIdx.x;

    // --- stage E tile (32 x 128 = 16KB), coalesced float4 ---
    const float* e = hE + (long long)n * (KNB * HDIM);
    #pragma unroll
    for (int i = 0; i < 8; i++) {
        int idx4 = t + 128 * i;
        int k  = idx4 >> 5;
        int a4 = idx4 & 31;
        float4 v = *(const float4*)&e[idx4 << 2];
        *(float4*)&Es[k * 132 + (a4 << 2)] = v;
    }
    // --- stage Qt (4 x 128) ---
    {
        const float* q = Qt + (long long)n * 512;
        int h  = t >> 5;
        int a4 = t & 31;
        *(float4*)&Qts[h * 132 + (a4 << 2)] = *(const float4*)&q[t << 2];
    }
    if (t < 32) msk[t] = mask[(long long)n * KNB + t];
    __syncthreads();

    // --- logits partials: warp ac covers a in [32*ac, 32*ac+32), lane = k ---
    {
        const int ac = t >> 5;        // a-chunk (warp)
        const int k  = t & 31;        // neighbor
        const float* ep = &Es[k * 132 + (ac << 5)];
        float p0 = 0.f, p1 = 0.f, p2 = 0.f, p3 = 0.f;
        #pragma unroll
        for (int s = 0; s < 8; s++) {
            float4 e4 = *(const float4*)&ep[s << 2];
            int ao = (ac << 5) + (s << 2);
            float4 q0 = *(const float4*)&Qts[0 * 132 + ao];  // warp-uniform
            float4 q1 = *(const float4*)&Qts[1 * 132 + ao];
            float4 q2 = *(const float4*)&Qts[2 * 132 + ao];
            float4 q3 = *(const float4*)&Qts[3 * 132 + ao];
            p0 += q0.x * e4.x + q0.y * e4.y + q0.z * e4.z + q0.w * e4.w;
            p1 += q1.x * e4.x + q1.y * e4.y + q1.z * e4.z + q1.w * e4.w;
            p2 += q2.x * e4.x + q2.y * e4.y + q2.z * e4.z + q2.w * e4.w;
            p3 += q3.x * e4.x + q3.y * e4.y + q3.z * e4.z + q3.w * e4.w;
        }
        Lp[(ac << 7) + 0 * 32 + k] = p0;   // lane-striped: conflict-free
        Lp[(ac << 7) + 1 * 32 + k] = p1;
        Lp[(ac << 7) + 2 * 32 + k] = p2;
        Lp[(ac << 7) + 3 * 32 + k] = p3;
    }
    __syncthreads();

    // --- masked softmax: warp h handles head h, lane = k ---
    {
        const int h = t >> 5, k = t & 31;
        float x = Lp[0 * 128 + h * 32 + k] + Lp[1 * 128 + h * 32 + k]
                + Lp[2 * 128 + h * 32 + k] + Lp[3 * 128 + h * 32 + k];
        bool mv  = (msk[k] != 0);
        float xm = mv ? x : -3.402823466e+38f;
        float mx = xm;
        #pragma unroll
        for (int o = 16; o > 0; o >>= 1) mx = fmaxf(mx, __shfl_xor_sync(0xffffffffu, mx, o));
        float p = mv ? __expf(xm - mx) : 0.f;
        float sm = p;
        #pragma unroll
        for (int o = 16; o > 0; o >>= 1) sm += __shfl_xor_sync(0xffffffffu, sm, o);
        float inv = (sm > 0.f) ? (1.f / sm) : 0.f;
        Asm[h * 32 + k] = p * inv;
    }
    __syncthreads();

    // --- ctx: thread t owns column a=t; 4 head accumulators in registers ---
    {
        float c0 = 0.f, c1 = 0.f, c2 = 0.f, c3 = 0.f;
        #pragma unroll
        for (int k4 = 0; k4 < 8; k4++) {
            float4 a0 = *(const float4*)&Asm[0 * 32 + (k4 << 2)];
            float4 a1 = *(const float4*)&Asm[1 * 32 + (k4 << 2)];
            float4 a2 = *(const float4*)&Asm[2 * 32 + (k4 << 2)];
            float4 a3 = *(const float4*)&Asm[3 * 32 + (k4 << 2)];
            float w0[4] = {a0.x, a0.y, a0.z, a0.w};
            float w1[4] = {a1.x, a1.y, a1.z, a1.w};
            float w2[4] = {a2.x, a2.y, a2.z, a2.w};
            float w3[4] = {a3.x, a3.y, a3.z, a3.w};
            #pragma unroll
            for (int i = 0; i < 4; i++) {
                float ev = Es[((k4 << 2) + i) * 132 + t];
                c0 += w0[i] * ev;
                c1 += w1[i] * ev;
                c2 += w2[i] * ev;
                c3 += w3[i] * ev;
            }
        }
        float* cp = ctx + (long long)n * 512 + t;
        cp[0]   = c0;
        cp[128] = c1;
        cp[256] = c2;
        cp[384] = c3;
    }
}

// ----------------------------------------------------------------------------
extern "C" void kernel_launch(void* const* d_in, const int* in_sizes, int n_in,
                              void* d_out, int out_size)
{
    const float* hV   = (const float*)d_in[0];
    const float* hE   = (const float*)d_in[1];
    const int*   mask = (const int*)  d_in[2];
    const float* WQ   = (const float*)d_in[3];
    const float* WK   = (const float*)d_in[4];
    const float* WV   = (const float*)d_in[5];
    const float* WO   = (const float*)d_in[6];
    float*       out  = (float*)d_out;

    const int N = in_sizes[0] / HDIM;
    if (N <= 0) return;

    float *Q, *Qt, *Ctx, *Vout;
    cudaGetSymbolAddress((void**)&Q,    g_Q);
    cudaGetSymbolAddress((void**)&Qt,   g_Qt);
    cudaGetSymbolAddress((void**)&Ctx,  g_ctx);
    cudaGetSymbolAddress((void**)&Vout, g_vout);

    const int MB64  = (N + 63) / 64;
    const int MB128 = (N + 127) / 128;
    const float inv_sqrt_d = 0.17677669529663687f;  // 1/sqrt(32)

    // 1) Q = h_V @ W_Q^T
    sgemm_kernel<64, 128, 8, 8, 8, true><<<dim3(1, MB64, 1), 128>>>(
        hV, WQ, Q, N, 128, 128, 128, 128, 128, 0, 0, 0, 1.f);

    // 2) Qt[n, h*128+b] = (1/sqrt(d)) * Q[n,32h:32h+32] @ W_K[32h:32h+32,:]
    sgemm_kernel<64, 128, 8, 8, 8, false><<<dim3(1, MB64, 4), 128>>>(
        Q, WK, Qt, N, 128, 32, 128, 128, 512,
        /*aB=*/32, /*bB=*/32 * 128, /*cB=*/128, inv_sqrt_d);

    // 3) fused attention -> ctx[N,512]
    attn_kernel<<<N, 128>>>(hE, mask, Qt, Ctx);

    // 4) vout[n, 32h+j] = ctx[n, 128h:] @ W_V[32h+j,:]
    sgemm_kernel<128, 32, 16, 8, 4, true><<<dim3(1, MB128, 4), 128>>>(
        Ctx, WV, Vout, N, 32, 128, 512, 128, 128,
        /*aB=*/128, /*bB=*/32 * 128, /*cB=*/32, 1.f);

    // 5) out = vout @ W_O^T
    sgemm_kernel<64, 128, 8, 8, 8, true><<<dim3(1, MB64, 1), 128>>>(
        Vout, WO, out, N, 128, 128, 128, 128, 128, 0, 0, 0, 1.f);
}

// round 5
// speedup vs baseline: 1.2000x; 1.0327x over previous
#include <cuda_runtime.h>
#include <cuda_bf16.h>

// ----------------------------------------------------------------------------
// NeighborAttention, restructured (63 GFLOP -> 3.9 GFLOP):
//   Qt[n,h,:]  = (1/sqrt(32)) * (h_V[n] @ W_Q^T)[32h:32h+32] @ W_K[32h:32h+32,:]
//   logits     = Qt[n,h,:] . h_E[n,k,:]     (only where mask=1)
//   attend     = masked softmax
//   ctx[n,h,:] = sum_k attend * h_E[n,k,:]
//   vout       = ctx_h @ W_V_h^T ; out = vout @ W_O^T
// Mask-predicated h_E loads: masked-out neighbor rows are never read from DRAM.
// ----------------------------------------------------------------------------

#define MAXN 30720
#define HDIM 128
#define KNB 32

__device__ float g_Q[MAXN * 128];
__device__ float g_Qt[MAXN * 512];
__device__ float g_ctx[MAXN * 512];
__device__ float g_vout[MAXN * 128];

// ----------------------------------------------------------------------------
// Tiled SGEMM, 8x8 / 8x4 register microtiles.
// ----------------------------------------------------------------------------
template <int BM, int BN, int BK, int TM, int TN, bool TRANSB>
__global__ void __launch_bounds__((BM / TM) * (BN / TN)) sgemm_kernel(
    const float* __restrict__ A, const float* __restrict__ B, float* __restrict__ C,
    int M, int Nc, int K, int lda, int ldb, int ldc,
    long long aB, long long bB, long long cB, float alpha)
{
    constexpr int NT = (BM / TM) * (BN / TN);
    __shared__ float As[BK][BM + 4];
    __shared__ float Bs[BK][BN + 4];

    const long long bz = blockIdx.z;
    A += bz * aB; B += bz * bB; C += bz * cB;

    const int m0 = blockIdx.y * BM;
    const int n0 = blockIdx.x * BN;
    const int t  = threadIdx.x;
    const int tm = t / (BN / TN);
    const int tn = t % (BN / TN);

    float acc[TM][TN] = {};

    for (int k0 = 0; k0 < K; k0 += BK) {
        constexpr int A4 = (BM * BK) / (4 * NT);
        #pragma unroll
        for (int i = 0; i < A4; i++) {
            int idx4 = t + NT * i;
            int r  = idx4 / (BK / 4);
            int kc = (idx4 % (BK / 4)) * 4;
            float4 v = make_float4(0.f, 0.f, 0.f, 0.f);
            int gr = m0 + r;
            if (gr < M) v = *(const float4*)&A[(long long)gr * lda + k0 + kc];
            As[kc + 0][r] = v.x;
            As[kc + 1][r] = v.y;
            As[kc + 2][r] = v.z;
            As[kc + 3][r] = v.w;
        }
        if (!TRANSB) {
            constexpr int B4 = (BK * BN) / (4 * NT);
            #pragma unroll
            for (int i = 0; i < B4; i++) {
                int idx4 = t + NT * i;
                int kr = idx4 / (BN / 4);
                int nc = (idx4 % (BN / 4)) * 4;
                float4 v = make_float4(0.f, 0.f, 0.f, 0.f);
                if (n0 + nc < Nc) v = *(const float4*)&B[(long long)(k0 + kr) * ldb + n0 + nc];
                *(float4*)&Bs[kr][nc] = v;
            }
        } else {
            constexpr int B4 = (BN * BK) / (4 * NT);
            #pragma unroll
            for (int i = 0; i < B4; i++) {
                int idx4 = t + NT * i;
                int n  = idx4 / (BK / 4);
                int kc = (idx4 % (BK / 4)) * 4;
                float4 v = make_float4(0.f, 0.f, 0.f, 0.f);
                if (n0 + n < Nc) v = *(const float4*)&B[(long long)(n0 + n) * ldb + k0 + kc];
                Bs[kc + 0][n] = v.x;
                Bs[kc + 1][n] = v.y;
                Bs[kc + 2][n] = v.z;
                Bs[kc + 3][n] = v.w;
            }
        }
        __syncthreads();

        #pragma unroll
        for (int kk = 0; kk < BK; kk++) {
            float a[TM], b[TN];
            #pragma unroll
            for (int h = 0; h < TM / 4; h++) {
                float4 v = *(const float4*)&As[kk][tm * 4 + h * (BM / 2)];
                a[h * 4 + 0] = v.x; a[h * 4 + 1] = v.y;
                a[h * 4 + 2] = v.z; a[h * 4 + 3] = v.w;
            }
            #pragma unroll
            for (int h = 0; h < TN / 4; h++) {
                float4 v = *(const float4*)&Bs[kk][tn * 4 + h * (BN / 2)];
                b[h * 4 + 0] = v.x; b[h * 4 + 1] = v.y;
                b[h * 4 + 2] = v.z; b[h * 4 + 3] = v.w;
            }
            #pragma unroll
            for (int i = 0; i < TM; i++)
                #pragma unroll
                for (int j = 0; j < TN; j++)
                    acc[i][j] += a[i] * b[j];
        }
        __syncthreads();
    }

    #pragma unroll
    for (int i = 0; i < TM; i++) {
        int r = m0 + tm * 4 + (i / 4) * (BM / 2) + (i % 4);
        if (r >= M) continue;
        #pragma unroll
        for (int jh = 0; jh < TN / 4; jh++) {
            int c = n0 + tn * 4 + jh * (BN / 2);
            if (c < Nc) {
                float4 v = make_float4(acc[i][jh * 4 + 0] * alpha, acc[i][jh * 4 + 1] * alpha,
                                       acc[i][jh * 4 + 2] * alpha, acc[i][jh * 4 + 3] * alpha);
                *(float4*)&C[(long long)r * ldc + c] = v;
            }
        }
    }
}

// ----------------------------------------------------------------------------
// Fused neighbor attention, one block (128 threads) per node.
// Masked-out neighbor rows of h_E are never loaded from DRAM (zero-filled).
// ----------------------------------------------------------------------------
__global__ void __launch_bounds__(128) attn_kernel(
    const float* __restrict__ hE, const int* __restrict__ mask,
    const float* __restrict__ Qt, float* __restrict__ ctx)
{
    __shared__ float Es[32 * 132];
    __shared__ float Qts[4 * 132];
    __shared__ float Lp[512];      // [ac][h*32+k]
    __shared__ float Asm[128];
    __shared__ int   msk[32];

    const int n = blockIdx.x;
    const int t = threadIdx.x;

    if (t < 32) msk[t] = mask[(long long)n * KNB + t];
    // stage Qt (4 x 128) while mask lands
    {
        const float* q = Qt + (long long)n * 512;
        int h  = t >> 5;
        int a4 = t & 31;
        *(float4*)&Qts[h * 132 + (a4 << 2)] = *(const float4*)&q[t << 2];
    }
    __syncthreads();

    // --- stage E tile: row k loaded only if mask[k]!=0 (warp-uniform k) ---
    const float* e = hE + (long long)n * (KNB * HDIM);
    #pragma unroll
    for (int i = 0; i < 8; i++) {
        int idx4 = t + 128 * i;
        int k  = idx4 >> 5;              // uniform across the warp
        int a4 = idx4 & 31;
        float4 v = make_float4(0.f, 0.f, 0.f, 0.f);
        if (msk[k]) v = *(const float4*)&e[idx4 << 2];
        *(float4*)&Es[k * 132 + (a4 << 2)] = v;
    }
    __syncthreads();

    // --- logits partials: warp ac covers a-chunk, lane = k ---
    {
        const int ac = t >> 5;
        const int k  = t & 31;
        const float* ep = &Es[k * 132 + (ac << 5)];
        float p0 = 0.f, p1 = 0.f, p2 = 0.f, p3 = 0.f;
        #pragma unroll
        for (int s = 0; s < 8; s++) {
            float4 e4 = *(const float4*)&ep[s << 2];
            int ao = (ac << 5) + (s << 2);
            float4 q0 = *(const float4*)&Qts[0 * 132 + ao];  // warp-uniform
            float4 q1 = *(const float4*)&Qts[1 * 132 + ao];
            float4 q2 = *(const float4*)&Qts[2 * 132 + ao];
            float4 q3 = *(const float4*)&Qts[3 * 132 + ao];
            p0 += q0.x * e4.x + q0.y * e4.y + q0.z * e4.z + q0.w * e4.w;
            p1 += q1.x * e4.x + q1.y * e4.y + q1.z * e4.z + q1.w * e4.w;
            p2 += q2.x * e4.x + q2.y * e4.y + q2.z * e4.z + q2.w * e4.w;
            p3 += q3.x * e4.x + q3.y * e4.y + q3.z * e4.z + q3.w * e4.w;
        }
        Lp[(ac << 7) + 0 * 32 + k] = p0;
        Lp[(ac << 7) + 1 * 32 + k] = p1;
        Lp[(ac << 7) + 2 * 32 + k] = p2;
        Lp[(ac << 7) + 3 * 32 + k] = p3;
    }
    __syncthreads();

    // --- masked softmax: warp h handles head h, lane = k ---
    {
        const int h = t >> 5, k = t & 31;
        float x = Lp[0 * 128 + h * 32 + k] + Lp[1 * 128 + h * 32 + k]
                + Lp[2 * 128 + h * 32 + k] + Lp[3 * 128 + h * 32 + k];
        bool mv  = (msk[k] != 0);
        float xm = mv ? x : -3.402823466e+38f;
        float mx = xm;
        #pragma unroll
        for (int o = 16; o > 0; o >>= 1) mx = fmaxf(mx, __shfl_xor_sync(0xffffffffu, mx, o));
        float p = mv ? __expf(xm - mx) : 0.f;
        float sm = p;
        #pragma unroll
        for (int o = 16; o > 0; o >>= 1) sm += __shfl_xor_sync(0xffffffffu, sm, o);
        float inv = (sm > 0.f) ? (1.f / sm) : 0.f;
        Asm[h * 32 + k] = p * inv;
    }
    __syncthreads();

    // --- ctx: thread t owns column a=t; 4 head accumulators ---
    {
        float c0 = 0.f, c1 = 0.f, c2 = 0.f, c3 = 0.f;
        #pragma unroll
        for (int k4 = 0; k4 < 8; k4++) {
            float4 a0 = *(const float4*)&Asm[0 * 32 + (k4 << 2)];
            float4 a1 = *(const float4*)&Asm[1 * 32 + (k4 << 2)];
            float4 a2 = *(const float4*)&Asm[2 * 32 + (k4 << 2)];
            float4 a3 = *(const float4*)&Asm[3 * 32 + (k4 << 2)];
            float w0[4] = {a0.x, a0.y, a0.z, a0.w};
            float w1[4] = {a1.x, a1.y, a1.z, a1.w};
            float w2[4] = {a2.x, a2.y, a2.z, a2.w};
            float w3[4] = {a3.x, a3.y, a3.z, a3.w};
            #pragma unroll
            for (int i = 0; i < 4; i++) {
                float ev = Es[((k4 << 2) + i) * 132 + t];
                c0 += w0[i] * ev;
                c1 += w1[i] * ev;
                c2 += w2[i] * ev;
                c3 += w3[i] * ev;
            }
        }
        float* cp = ctx + (long long)n * 512 + t;
        cp[0]   = c0;
        cp[128] = c1;
        cp[256] = c2;
        cp[384] = c3;
    }
}

// ----------------------------------------------------------------------------
extern "C" void kernel_launch(void* const* d_in, const int* in_sizes, int n_in,
                              void* d_out, int out_size)
{
    const float* hV   = (const float*)d_in[0];
    const float* hE   = (const float*)d_in[1];
    const int*   mask = (const int*)  d_in[2];
    const float* WQ   = (const float*)d_in[3];
    const float* WK   = (const float*)d_in[4];
    const float* WV   = (const float*)d_in[5];
    const float* WO   = (const float*)d_in[6];
    float*       out  = (float*)d_out;

    const int N = in_sizes[0] / HDIM;
    if (N <= 0) return;

    float *Q, *Qt, *Ctx, *Vout;
    cudaGetSymbolAddress((void**)&Q,    g_Q);
    cudaGetSymbolAddress((void**)&Qt,   g_Qt);
    cudaGetSymbolAddress((void**)&Ctx,  g_ctx);
    cudaGetSymbolAddress((void**)&Vout, g_vout);

    const int MB64  = (N + 63) / 64;
    const int MB256 = (N + 255) / 256;
    const float inv_sqrt_d = 0.17677669529663687f;  // 1/sqrt(32)

    // 1) Q = h_V @ W_Q^T
    sgemm_kernel<64, 128, 16, 8, 8, true><<<dim3(1, MB64, 1), 128>>>(
        hV, WQ, Q, N, 128, 128, 128, 128, 128, 0, 0, 0, 1.f);

    // 2) Qt[n, h*128+b] = (1/sqrt(d)) * Q[n,32h:32h+32] @ W_K[32h:32h+32,:]
    sgemm_kernel<64, 128, 16, 8, 8, false><<<dim3(1, MB64, 4), 128>>>(
        Q, WK, Qt, N, 128, 32, 128, 128, 512,
        /*aB=*/32, /*bB=*/32 * 128, /*cB=*/128, inv_sqrt_d);

    // 3) fused attention -> ctx[N,512]
    attn_kernel<<<N, 128>>>(hE, mask, Qt, Ctx);

    // 4) vout[n, 32h+j] = ctx[n, 128h:] @ W_V[32h+j,:]   (8x8 microtile, BM=256)
    sgemm_kernel<256, 32, 16, 8, 8, true><<<dim3(1, MB256, 4), 128>>>(
        Ctx, WV, Vout, N, 32, 128, 512, 128, 128,
        /*aB=*/128, /*bB=*/32 * 128, /*cB=*/32, 1.f);

    // 5) out = vout @ W_O^T
    sgemm_kernel<64, 128, 16, 8, 8, true><<<dim3(1, MB64, 1), 128>>>(
        Vout, WO, out, N, 128, 128, 128, 128, 128, 0, 0, 0, 1.f);
}